// round 6
// baseline (speedup 1.0000x reference)
#include <cuda_runtime.h>

// Packed fp32x2 FMA (Blackwell sm_103a): 2x fp32 throughput vs scalar FFMA.
#define FMA2(d, a, b, c) \
    asm("fma.rn.f32x2 %0, %1, %2, %3;" : "=l"(d) : "l"(a), "l"(b), "l"(c))

// Problem constants (shapes fixed by the dataset)
// imgs: (32, 3, 512, 512) f32; weight: (512, 16384) f32; bias: (512) f32
// feats: (32, 16384) f32 ; out: (32, 512) f32
#define BATCH    32
#define KDIM     16384
#define NDIM     512
#define NSPLIT   128      // split-K factor
#define KCHUNK   128      // K per GEMM block  (NSPLIT*KCHUNK == KDIM)
#define KS       32       // K per smem stage
#define NT       128      // N tile per GEMM block

// Scratch (device globals: no allocation allowed in kernel_launch)
__device__ float g_feats[BATCH * KDIM];                 // 2 MB, [b][k]
__device__ float g_part[NSPLIT * BATCH * NDIM];         // 8 MB, [ks][m][n]

// ---------------------------------------------------------------------------
// Kernel 1: per-8x8-block features. Only dct[0, 0:4] survives:
//   s[l] = sum_a X[a][l];  f_m = (1/8) * sum_l s[l] * cos(pi*m*l/4)
// One thread per (batch, block). tid = b*4096 + (i*64 + j) so both the image
// reads and the float4 feats stores are coalesced.
// ---------------------------------------------------------------------------
__global__ __launch_bounds__(256) void feats_kernel(const float* __restrict__ img)
{
    int tid = blockIdx.x * 256 + threadIdx.x;   // 0 .. 131071
    int b  = tid >> 12;                          // batch
    int ij = tid & 4095;                         // block index (i*64 + j)
    int i  = ij >> 6;
    int j  = ij & 63;

    // channel 0 of image b: offset b*3*512*512
    const float* p = img + (size_t)b * 786432 + (size_t)(i * 8) * 512 + j * 8;

    float s0 = 0.f, s1 = 0.f, s2 = 0.f, s3 = 0.f;
    float s4 = 0.f, s5 = 0.f, s6 = 0.f, s7 = 0.f;
#pragma unroll
    for (int r = 0; r < 8; r++) {
        float4 lo = *(const float4*)(p + r * 512);
        float4 hi = *(const float4*)(p + r * 512 + 4);
        s0 += lo.x; s1 += lo.y; s2 += lo.z; s3 += lo.w;
        s4 += hi.x; s5 += hi.y; s6 += hi.z; s7 += hi.w;
    }

    const float R = 0.70710678118654752f;  // cos(pi/4)
    float e = s0 - s4;
    float o = s1 - s3 - s5 + s7;
    float4 f;
    f.x = 0.125f * (((s0 + s1) + (s2 + s3)) + ((s4 + s5) + (s6 + s7)));
    f.y = 0.125f * (e + R * o);
    f.z = 0.125f * ((s0 - s2) + (s4 - s6));
    f.w = 0.125f * (e - R * o);

    *(float4*)&g_feats[(size_t)b * KDIM + ij * 4] = f;
}

// ---------------------------------------------------------------------------
// Kernel 2: split-K GEMM partials.  part[ks][m][n] = sum_{k in chunk} A[m][k]*W[n][k]
// Block tile: M=32 x N=128 over KCHUNK=128.  grid = (NDIM/NT, NSPLIT) = (4,128).
// Per thread: 4m x 4n accumulators, packed f32x2 over k-pairs (even k in lane0,
// odd k in lane1; folded at the end). Inner loop: 8 LDS.64 + 16 FFMA2 per 32 MACs.
// ---------------------------------------------------------------------------
__global__ __launch_bounds__(256) void gemm_kernel(const float* __restrict__ W)
{
    // Strides chosen so every 8B/16B access is aligned and w-loads are at most
    // 2-way bank conflicted; a-loads are warp-uniform (broadcast).
    __shared__ __align__(16) float As[32 * 36];   // [m][k], stride 36
    __shared__ __align__(16) float Ws[NT * 34];   // [n][k], stride 34

    const int t  = threadIdx.x;
    const int n0 = blockIdx.x * NT;
    const int ks = blockIdx.y;
    const int k0 = ks * KCHUNK;
    const int tx = t & 31;         // n lane
    const int ty = t >> 5;         // m group (0..7)
    const int m0 = ty * 4;

    unsigned long long acc[4][4];
#pragma unroll
    for (int mi = 0; mi < 4; mi++)
#pragma unroll
        for (int q = 0; q < 4; q++) acc[mi][q] = 0ULL;  // packed (+0.f, +0.f)

    for (int kk = 0; kk < KCHUNK; kk += KS) {
        const int kb = k0 + kk;

        // stage A: 32m x 32k (coalesced LDG.128, aligned STS.128)
        {
            int m = t >> 3, kq = t & 7;
            float4 v = *(const float4*)&g_feats[(size_t)m * KDIM + kb + kq * 4];
            *(float4*)&As[m * 36 + kq * 4] = v;
        }
        // stage W: 128n x 32k in 4 passes (coalesced LDG.128, STS.64 pairs)
#pragma unroll
        for (int p = 0; p < 4; p++) {
            int n = (t >> 3) + p * 32, kq = t & 7;
            float4 v = *(const float4*)&W[(size_t)(n0 + n) * KDIM + kb + kq * 4];
            float2* dst = (float2*)&Ws[n * 34 + kq * 4];
            dst[0] = make_float2(v.x, v.y);
            dst[1] = make_float2(v.z, v.w);
        }
        __syncthreads();

#pragma unroll
        for (int k = 0; k < KS; k += 2) {
            unsigned long long a2[4], w2[4];
#pragma unroll
            for (int mi = 0; mi < 4; mi++)
                a2[mi] = *(const unsigned long long*)&As[(m0 + mi) * 36 + k];
#pragma unroll
            for (int q = 0; q < 4; q++)
                w2[q] = *(const unsigned long long*)&Ws[(tx + 32 * q) * 34 + k];
#pragma unroll
            for (int mi = 0; mi < 4; mi++)
#pragma unroll
                for (int q = 0; q < 4; q++)
                    FMA2(acc[mi][q], a2[mi], w2[q], acc[mi][q]);
        }
        __syncthreads();
    }

    // fold even/odd-k lanes and write partials (coalesced across tx)
#pragma unroll
    for (int mi = 0; mi < 4; mi++) {
#pragma unroll
        for (int q = 0; q < 4; q++) {
            unsigned long long v = acc[mi][q];
            float lo = __uint_as_float((unsigned int)(v & 0xffffffffULL));
            float hi = __uint_as_float((unsigned int)(v >> 32));
            g_part[(size_t)ks * (BATCH * NDIM) + (m0 + mi) * NDIM + n0 + tx + 32 * q] =
                lo + hi;
        }
    }
}

// ---------------------------------------------------------------------------
// Kernel 3: deterministic split-K reduction + bias.  out[m][n] (16384 values)
// ---------------------------------------------------------------------------
__global__ __launch_bounds__(256) void reduce_kernel(const float* __restrict__ bias,
                                                     float* __restrict__ out)
{
    int i = blockIdx.x * 256 + threadIdx.x;   // 0 .. 16383
    float a0 = 0.f, a1 = 0.f, a2 = 0.f, a3 = 0.f;
#pragma unroll
    for (int ks = 0; ks < NSPLIT; ks += 4) {
        a0 += g_part[(size_t)(ks + 0) * (BATCH * NDIM) + i];
        a1 += g_part[(size_t)(ks + 1) * (BATCH * NDIM) + i];
        a2 += g_part[(size_t)(ks + 2) * (BATCH * NDIM) + i];
        a3 += g_part[(size_t)(ks + 3) * (BATCH * NDIM) + i];
    }
    out[i] = ((a0 + a1) + (a2 + a3)) + bias[i & (NDIM - 1)];
}

// ---------------------------------------------------------------------------
extern "C" void kernel_launch(void* const* d_in, const int* in_sizes, int n_in,
                              void* d_out, int out_size)
{
    const float* img    = (const float*)d_in[0];
    const float* weight = (const float*)d_in[1];
    const float* bias   = (const float*)d_in[2];
    float* out = (float*)d_out;

    feats_kernel<<<512, 256>>>(img);                       // 131072 threads
    gemm_kernel<<<dim3(NDIM / NT, NSPLIT), 256>>>(weight); // (4,128) blocks
    reduce_kernel<<<(BATCH * NDIM) / 256, 256>>>(bias, out);
}